// round 13
// baseline (speedup 1.0000x reference)
#include <cuda_runtime.h>
#include <cuda_bf16.h>
#include <math_constants.h>

#define N_TOKENS   8192
#define QUANT_DIM  8192
#define OUTPUT_DIM 1024
#define SEC_COLS   32                     // one full 128B line per sector
#define N_SECTORS  (QUANT_DIM / SEC_COLS) // 256
#define SLICE_ROWS 64
#define N_SLICES   (OUTPUT_DIM / SLICE_ROWS)  // 16
#define LIST_CHUNK 1024

// Scratch (__device__ globals: allocation-free, zero-initialized at load).
// Invariant maintained by the gather kernel: g_cnt/g_done are zero at the
// start of every replay (16th slice-block per sector resets them).
__device__ int g_cnt[N_SECTORS];
__device__ int g_done[N_SECTORS];
__device__ int g_list[(size_t)N_SECTORS * N_TOKENS];   // packed (row<<5)|off

// ---------------------------------------------------------------------------
// Kernel 1: pure streaming argmax, one block per row. First-index tie-break
// (jnp.argmax). Winner pushed into its 32-column sector's token list.
// ---------------------------------------------------------------------------
__global__ __launch_bounds__(256) void argmax_rows_kernel(
    const float* __restrict__ x)
{
    const int row = blockIdx.x;
    const float4* __restrict__ xr =
        reinterpret_cast<const float4*>(x + (size_t)row * QUANT_DIM);

    float best = -CUDART_INF_F;
    int   bidx = 0;

    #pragma unroll
    for (int it = 0; it < 8; ++it) {
        const int i = threadIdx.x + it * 256;
        const float4 v = __ldcs(&xr[i]);           // streaming read
        const float vm = fmaxf(fmaxf(v.x, v.y), fmaxf(v.z, v.w));
        if (vm > best) {                            // rare after warmup
            best = vm;
            const int base = i * 4;
            bidx = (v.x == vm) ? base
                 : (v.y == vm) ? base + 1
                 : (v.z == vm) ? base + 2
                 :               base + 3;          // first-equal = first index
        }
    }

    #pragma unroll
    for (int off = 16; off > 0; off >>= 1) {
        float ov = __shfl_down_sync(0xFFFFFFFFu, best, off);
        int   oi = __shfl_down_sync(0xFFFFFFFFu, bidx, off);
        if (ov > best || (ov == best && oi < bidx)) { best = ov; bidx = oi; }
    }

    __shared__ float s_val[8];
    __shared__ int   s_idx[8];
    const int lane = threadIdx.x & 31;
    const int warp = threadIdx.x >> 5;
    if (lane == 0) { s_val[warp] = best; s_idx[warp] = bidx; }
    __syncthreads();

    if (warp == 0) {
        best = (lane < 8) ? s_val[lane] : -CUDART_INF_F;
        bidx = (lane < 8) ? s_idx[lane] : 0x7FFFFFFF;
        #pragma unroll
        for (int off = 4; off > 0; off >>= 1) {
            float ov = __shfl_down_sync(0xFFFFFFFFu, best, off);
            int   oi = __shfl_down_sync(0xFFFFFFFFu, bidx, off);
            if (ov > best || (ov == best && oi < bidx)) { best = ov; bidx = oi; }
        }
        if (lane == 0) {
            const int sec  = bidx >> 5;
            const int slot = atomicAdd(&g_cnt[sec], 1);
            g_list[((size_t)sec << 13) + slot] = (row << 5) | (bidx & 31);
        }
    }
}

// ---------------------------------------------------------------------------
// Kernel 2: full-line sector gather. Block (sec, slice) loads the
// 64-row x 32-col slice W[slice*64 .. +64, sec*32 .. +32] -- every 128B line
// fully consumed -- into a stride-33 smem tile, stages the sector's token
// list into smem, then emits each token's 64-float output chunk
// (conflict-free LDS + 256B coalesced streaming STG).
// Counter reset: per-sector done counter; 16th arrival resets (the
// __threadfence orders every block's count-read before its arrival, so the
// reset can never clobber an unread count). No extra kernel, no hot atomic.
// ---------------------------------------------------------------------------
__global__ __launch_bounds__(256) void sector_gather_kernel(
    const float* __restrict__ W, float* __restrict__ out)
{
    __shared__ float tile[SLICE_ROWS * 33];   // stride 33: conflict-free picks
    __shared__ int   s_list[LIST_CHUNK];
    __shared__ int   s_cnt;

    const int sec   = blockIdx.x;
    const int slice = blockIdx.y;
    const int tid   = threadIdx.x;

    // Counter read + distributed last-done reset.
    if (tid == 0) {
        const int c = g_cnt[sec];              // stream-ordered after argmax
        s_cnt = c;
        __threadfence();                        // read happens-before arrival
        const int d = atomicAdd(&g_done[sec], 1);
        if (d == N_SLICES - 1) { g_cnt[sec] = 0; g_done[sec] = 0; }
    }

    // Fill tile: 64 rows x 32 floats = 512 float4 slots, 2 per thread.
    #pragma unroll
    for (int it = 0; it < 2; ++it) {
        const int s  = tid + it * 256;
        const int r  = s >> 3;                 // row in slice (0..63)
        const int k4 = s & 7;                  // float4 within row
        const float4 v = __ldcs(reinterpret_cast<const float4*>(
            W + (size_t)(slice * SLICE_ROWS + r) * QUANT_DIM
              + sec * SEC_COLS + k4 * 4));
        tile[r * 33 + k4 * 4 + 0] = v.x;
        tile[r * 33 + k4 * 4 + 1] = v.y;
        tile[r * 33 + k4 * 4 + 2] = v.z;
        tile[r * 33 + k4 * 4 + 3] = v.w;
    }
    __syncthreads();

    const int cnt = s_cnt;
    const int q     = tid >> 6;                // 4 tokens per iteration
    const int c_loc = tid & 63;

    for (int base = 0; base < cnt; base += LIST_CHUNK) {
        const int chunk = min(cnt - base, LIST_CHUNK);
        for (int j = tid; j < chunk; j += 256)
            s_list[j] = g_list[((size_t)sec << 13) + base + j];
        __syncthreads();

        for (int t = q; t < chunk; t += 4) {
            const int e     = s_list[t];
            const int token = e >> 5;
            const int off   = e & 31;
            const float val = tile[c_loc * 33 + off];        // conflict-free
            __stcs(&out[(size_t)token * OUTPUT_DIM
                        + slice * SLICE_ROWS + c_loc], val); // 256B coalesced
        }
        __syncthreads();                        // s_list reuse guard
    }
}

// ---------------------------------------------------------------------------
extern "C" void kernel_launch(void* const* d_in, const int* in_sizes, int n_in,
                              void* d_out, int out_size)
{
    const float* x = (const float*)d_in[0];   // [8192, 8192] fp32
    const float* W = (const float*)d_in[1];   // [1024, 8192] fp32
    float* out = (float*)d_out;               // [8192, 1024] fp32

    argmax_rows_kernel<<<N_TOKENS, 256>>>(x);
    sector_gather_kernel<<<dim3(N_SECTORS, N_SLICES), 256>>>(W, out);
}